// round 3
// baseline (speedup 1.0000x reference)
#include <cuda_runtime.h>
#include <math.h>

#define NBA 10
#define NCLS 14
#define LCH 19
#define NOBJ 256
#define BB 8
#define HH 96
#define WW 96
#define CC (NBA*LCH)          // 190
#define HWSZ (HH*WW)          // 9216
#define TOTAL (BB*NBA*HH*WW)  // 737280
#define NRED 720              // reduce blocks (720*256*4 == TOTAL)
#define NIOU 10               // gather blocks (10*256 == NOBJ*NBA)

// Staging (rewritten every replay -> deterministic, no zeroing needed)
__device__ float g_part[NRED];
__device__ float g_iou  [NOBJ*NBA];
__device__ float g_pc   [NOBJ*NBA];
__device__ float g_px   [NOBJ*NBA];
__device__ float g_py   [NOBJ*NBA];
__device__ float g_pw   [NOBJ*NBA];
__device__ float g_ph   [NOBJ*NBA];
__device__ float g_tconf[NOBJ*NBA];           // T conf at channel a*LCH
__device__ float g_pcls [NOBJ*NBA*NCLS];      // pred class vals per anchor
__device__ float g_tc[NOBJ], g_tx[NOBJ], g_ty[NOBJ], g_tw[NOBJ], g_th[NOBJ];
__device__ float g_tcls [NOBJ*NCLS];          // target class (bug-preserved chan b*LCH+5)

// ---------------------------------------------------------------------------
// Kernel A: blocks [0,720) dense (tc-pc)^2 reduction; blocks [720,730) do the
// per-(grid,anchor) IoU AND stage every gather value the finalize kernel needs.
// ---------------------------------------------------------------------------
__global__ void kA(const float* __restrict__ P, const float* __restrict__ T,
                   const int* __restrict__ G) {
    int bid = blockIdx.x, tid = threadIdx.x;

    if (bid < NRED) {
        int idx = bid * 256 + tid;            // 0 .. TOTAL/4-1
        int plane = idx / (HWSZ/4);
        int off   = idx % (HWSZ/4);
        int b = plane / NBA, a = plane % NBA;
        size_t base = (size_t)(b*CC + a*LCH) * HWSZ + (size_t)off * 4;
        float4 t = *reinterpret_cast<const float4*>(T + base);
        float4 p = *reinterpret_cast<const float4*>(P + base);
        float dx = t.x - p.x, dy = t.y - p.y, dz = t.z - p.z, dw = t.w - p.w;
        float s = dx*dx + dy*dy + dz*dz + dw*dw;
        #pragma unroll
        for (int o = 16; o; o >>= 1) s += __shfl_down_sync(0xffffffffu, s, o);
        __shared__ float ws[8];
        int lane = tid & 31, wd = tid >> 5;
        if (lane == 0) ws[wd] = s;
        __syncthreads();
        if (tid == 0) {
            float bs = 0.0f;
            #pragma unroll
            for (int k = 0; k < 8; k++) bs += ws[k];
            g_part[bid] = bs;
        }
        return;
    }

    // ---- gather/IoU path ----
    int idx = (bid - NRED) * 256 + tid;       // 0 .. 2559
    int i = idx / NBA, a = idx % NBA;
    int b = G[i*4+0], g = G[i*4+1], h = G[i*4+2], w = G[i*4+3];
    int base = h * WW + w;

    const float* Tg = T + (size_t)(b*CC + g*LCH)*HWSZ + base;
    float tx = Tg[1*HWSZ], ty = Tg[2*HWSZ], tw = Tg[3*HWSZ], th = Tg[4*HWSZ];

    const float* Pa = P + (size_t)(b*CC + a*LCH)*HWSZ + base;
    float pc = Pa[0];
    float px = Pa[1*HWSZ], py = Pa[2*HWSZ], pw = Pa[3*HWSZ], ph = Pa[4*HWSZ];

    // IoU of corner boxes
    float tx1 = tx - tw*0.5f, ty1 = ty - th*0.5f, tx2 = tx + tw*0.5f, ty2 = ty + th*0.5f;
    float px1 = px - pw*0.5f, py1 = py - ph*0.5f, px2 = px + pw*0.5f, py2 = py + ph*0.5f;
    float x1 = fmaxf(tx1, px1), y1 = fmaxf(ty1, py1);
    float x2 = fminf(tx2, px2), y2 = fminf(ty2, py2);
    float inter = fmaxf(x2 - x1, 0.0f) * fmaxf(y2 - y1, 0.0f);
    float a1 = fabsf((tx2 - tx1) * (ty2 - ty1));
    float a2 = fabsf((px2 - px1) * (py2 - py1));
    g_iou[idx] = inter / (a1 + a2 - inter + 1e-6f);

    g_pc[idx] = pc; g_px[idx] = px; g_py[idx] = py; g_pw[idx] = pw; g_ph[idx] = ph;
    g_tconf[idx] = T[(size_t)(b*CC + a*LCH)*HWSZ + base];
    #pragma unroll
    for (int c = 0; c < NCLS; c++)
        g_pcls[idx*NCLS + c] = Pa[(size_t)(5 + c)*HWSZ];

    if (a == 0) {
        g_tc[i] = Tg[0]; g_tx[i] = tx; g_ty[i] = ty; g_tw[i] = tw; g_th[i] = th;
        const float* Tcls = T + (size_t)(b*CC + b*LCH + 5)*HWSZ + base;
        #pragma unroll
        for (int c = 0; c < NCLS; c++)
            g_tcls[i*NCLS + c] = Tcls[(size_t)c*HWSZ];
    }
}

// ---------------------------------------------------------------------------
// Kernel B: one block, 256 threads. Sequential anchor selection, sel_xy,
// dedup, per-grid losses from STAGED data only, final combine.
// ---------------------------------------------------------------------------
__global__ void kB(const int* __restrict__ G, float* __restrict__ out) {
    __shared__ int    sB[NOBJ], sG[NOBJ], sH[NOBJ], sW[NOBJ];
    __shared__ float  sIou[NOBJ*NBA];
    __shared__ int    sSel[NOBJ], sSelxy[NOBJ], sIndep[NOBJ];
    __shared__ int    sMask[BB*NBA*NBA];
    __shared__ float  sRed[4][8];
    __shared__ double sDAll[8];
    int tid = threadIdx.x;

    sB[tid] = G[tid*4+0]; sG[tid] = G[tid*4+1];
    sH[tid] = G[tid*4+2]; sW[tid] = G[tid*4+3];
    for (int k = tid; k < NOBJ*NBA; k += 256) sIou[k] = g_iou[k];
    for (int k = tid; k < BB*NBA*NBA; k += 256) sMask[k] = 0;

    // Dense-reduction partial sum (720 slots)
    double dsum = 0.0;
    for (int k = tid; k < NRED; k += 256) dsum += (double)g_part[k];
    #pragma unroll
    for (int o = 16; o; o >>= 1) dsum += __shfl_down_sync(0xffffffffu, dsum, o);
    if ((tid & 31) == 0) sDAll[tid >> 5] = dsum;
    __syncthreads();

    // Independent selection result (valid when read-row (b,h,w) unwritable: w>=NBA)
    {
        int r = 0;
        #pragma unroll
        for (int a = 1; a < NBA; a++)
            if (r == 0 && sIou[tid*NBA + a] > 0.0f) r = a;
        sIndep[tid] = r;
    }
    __syncthreads();

    // Sequential pass in scan order (thread 0)
    if (tid == 0) {
        for (int i = 0; i < NOBJ; i++) {
            int b = sB[i], g = sG[i], h = sH[i], w = sW[i];
            int res;
            if (w < NBA) {
                int m = sMask[(b*NBA + h)*NBA + w];
                res = 0;
                #pragma unroll
                for (int a = 1; a < NBA; a++)
                    if (res == 0 && sIou[i*NBA + a] > 0.0f && !((m >> a) & 1))
                        res = a;
            } else {
                res = sIndep[i];
            }
            if (res) sMask[(b*NBA + g)*NBA + h] |= (1 << res);
            sSel[i] = res;
        }
    }
    __syncthreads();

    // sel_xy[i] = final maxI[b, g, h, h] (bug-preserved double-h index)
    {
        int b = sB[tid], g = sG[tid], h = sH[tid];
        int v = 0;
        for (int j = 0; j < NOBJ; j++)
            if (sB[j] == b && sG[j] == g && sH[j] == h && sW[j] == h) v = sSel[j];
        sSelxy[tid] = v;
    }
    __syncthreads();

    // Per-grid loss terms from staged data
    int b = sB[tid], h = sH[tid], w = sW[tid];
    int sel = sSel[tid], sxy = sSelxy[tid];
    int ib = tid*NBA;

    float tx = g_tx[tid], ty = g_ty[tid], tw = g_tw[tid], th = g_th[tid];
    float tc = g_tc[tid];
    float px = g_px[ib + sxy], py = g_py[ib + sxy];
    float pc = g_pc[ib + sel], pw = g_pw[ib + sel], ph = g_ph[ib + sel];

    float xl = (tx - px) * (tx - px);
    float yl = (ty - py) * (ty - py);
    float swt = sqrtf(fmaxf(tw, 0.0f)), swp = sqrtf(fmaxf(pw, 0.0f));
    float sht = sqrtf(fmaxf(th, 0.0f)), shp = sqrtf(fmaxf(ph, 0.0f));
    float loc  = xl + yl + (swt - swp)*(swt - swp) + (sht - shp)*(sht - shp);
    float cobj = (tc - pc) * (tc - pc);

    float cls = 0.0f;
    #pragma unroll
    for (int c = 0; c < NCLS; c++) {
        float d = g_pcls[(ib + sel)*NCLS + c] - g_tcls[tid*NCLS + c];
        cls += d * d;
    }
    cls *= (1.0f / NCLS);

    // conf_nothing correction (dedup: first occurrence in scan order wins)
    float tcs = g_tconf[ib + sel];
    float corr = (tcs - pc) * (tcs - pc);
    for (int j = 0; j < tid; j++)
        if (sB[j] == b && sH[j] == h && sW[j] == w && sSel[j] == sel) { corr = 0.0f; break; }

    float v0 = loc, v1 = cobj, v2 = cls, v3 = corr;
    #pragma unroll
    for (int o = 16; o; o >>= 1) {
        v0 += __shfl_down_sync(0xffffffffu, v0, o);
        v1 += __shfl_down_sync(0xffffffffu, v1, o);
        v2 += __shfl_down_sync(0xffffffffu, v2, o);
        v3 += __shfl_down_sync(0xffffffffu, v3, o);
    }
    int lane = tid & 31, wd = tid >> 5;
    if (lane == 0) { sRed[0][wd] = v0; sRed[1][wd] = v1; sRed[2][wd] = v2; sRed[3][wd] = v3; }
    __syncthreads();
    if (tid == 0) {
        float L = 0, Cq = 0, Cl = 0, Co = 0;
        double all = 0.0;
        #pragma unroll
        for (int k = 0; k < 8; k++) {
            L += sRed[0][k]; Cq += sRed[1][k]; Cl += sRed[2][k]; Co += sRed[3][k];
            all += sDAll[k];
        }
        double nothing = (all - (double)Co) / (double)TOTAL;
        out[0] = 7.0f * (L / NOBJ) + 5.0f * (Cq / NOBJ)
               + 5.0f * (float)nothing + (Cl / NOBJ);
    }
}

extern "C" void kernel_launch(void* const* d_in, const int* in_sizes, int n_in,
                              void* d_out, int out_size) {
    const float* P = (const float*)d_in[0];
    const float* T = (const float*)d_in[1];
    const int*   G = (const int*)d_in[2];
    float* out = (float*)d_out;

    kA<<<NRED + NIOU, 256>>>(P, T, G);
    kB<<<1, 256>>>(G, out);
}

// round 4
// speedup vs baseline: 3.3984x; 3.3984x over previous
#include <cuda_runtime.h>
#include <math.h>

#define NBA 10
#define NCLS 14
#define LCH 19
#define NOBJ 256
#define BB 8
#define HH 96
#define WW 96
#define CC (NBA*LCH)          // 190
#define HWSZ (HH*WW)          // 9216
#define TOTAL (BB*NBA*HH*WW)  // 737280
#define NRED 720              // reduce blocks (720*256*4 == TOTAL)
#define NIOU 10               // gather blocks (10*256 == NOBJ*NBA)

// Staging (rewritten every replay -> deterministic, no zeroing needed)
__device__ float g_part[NRED];
__device__ float g_iou  [NOBJ*NBA];
__device__ float g_pc   [NOBJ*NBA];
__device__ float g_px   [NOBJ*NBA];
__device__ float g_py   [NOBJ*NBA];
__device__ float g_pw   [NOBJ*NBA];
__device__ float g_ph   [NOBJ*NBA];
__device__ float g_tconf[NOBJ*NBA];           // T conf at channel a*LCH
__device__ float g_pcls [NOBJ*NBA*NCLS];      // pred class vals per anchor
__device__ float g_tc[NOBJ], g_tx[NOBJ], g_ty[NOBJ], g_tw[NOBJ], g_th[NOBJ];
__device__ float g_tcls [NOBJ*NCLS];          // target class (bug-preserved chan b*LCH+5)

// ---------------------------------------------------------------------------
// Kernel A: blocks [0,720) dense (tc-pc)^2 reduction; blocks [720,730) do the
// per-(grid,anchor) IoU AND stage every gather value the finalize kernel needs.
// ---------------------------------------------------------------------------
__global__ void kA(const float* __restrict__ P, const float* __restrict__ T,
                   const int* __restrict__ G) {
    int bid = blockIdx.x, tid = threadIdx.x;

    if (bid < NRED) {
        int idx = bid * 256 + tid;            // 0 .. TOTAL/4-1
        int plane = idx / (HWSZ/4);
        int off   = idx % (HWSZ/4);
        int b = plane / NBA, a = plane % NBA;
        size_t base = (size_t)(b*CC + a*LCH) * HWSZ + (size_t)off * 4;
        float4 t = *reinterpret_cast<const float4*>(T + base);
        float4 p = *reinterpret_cast<const float4*>(P + base);
        float dx = t.x - p.x, dy = t.y - p.y, dz = t.z - p.z, dw = t.w - p.w;
        float s = dx*dx + dy*dy + dz*dz + dw*dw;
        #pragma unroll
        for (int o = 16; o; o >>= 1) s += __shfl_down_sync(0xffffffffu, s, o);
        __shared__ float ws[8];
        int lane = tid & 31, wd = tid >> 5;
        if (lane == 0) ws[wd] = s;
        __syncthreads();
        if (tid == 0) {
            float bs = 0.0f;
            #pragma unroll
            for (int k = 0; k < 8; k++) bs += ws[k];
            g_part[bid] = bs;
        }
        return;
    }

    // ---- gather/IoU path ----
    int idx = (bid - NRED) * 256 + tid;       // 0 .. 2559
    int i = idx / NBA, a = idx % NBA;
    int b = G[i*4+0], g = G[i*4+1], h = G[i*4+2], w = G[i*4+3];
    int base = h * WW + w;

    const float* Tg = T + (size_t)(b*CC + g*LCH)*HWSZ + base;
    float tx = Tg[1*HWSZ], ty = Tg[2*HWSZ], tw = Tg[3*HWSZ], th = Tg[4*HWSZ];

    const float* Pa = P + (size_t)(b*CC + a*LCH)*HWSZ + base;
    float pc = Pa[0];
    float px = Pa[1*HWSZ], py = Pa[2*HWSZ], pw = Pa[3*HWSZ], ph = Pa[4*HWSZ];

    // IoU of corner boxes
    float tx1 = tx - tw*0.5f, ty1 = ty - th*0.5f, tx2 = tx + tw*0.5f, ty2 = ty + th*0.5f;
    float px1 = px - pw*0.5f, py1 = py - ph*0.5f, px2 = px + pw*0.5f, py2 = py + ph*0.5f;
    float x1 = fmaxf(tx1, px1), y1 = fmaxf(ty1, py1);
    float x2 = fminf(tx2, px2), y2 = fminf(ty2, py2);
    float inter = fmaxf(x2 - x1, 0.0f) * fmaxf(y2 - y1, 0.0f);
    float a1 = fabsf((tx2 - tx1) * (ty2 - ty1));
    float a2 = fabsf((px2 - px1) * (py2 - py1));
    g_iou[idx] = inter / (a1 + a2 - inter + 1e-6f);

    g_pc[idx] = pc; g_px[idx] = px; g_py[idx] = py; g_pw[idx] = pw; g_ph[idx] = ph;
    g_tconf[idx] = T[(size_t)(b*CC + a*LCH)*HWSZ + base];
    #pragma unroll
    for (int c = 0; c < NCLS; c++)
        g_pcls[idx*NCLS + c] = Pa[(size_t)(5 + c)*HWSZ];

    if (a == 0) {
        g_tc[i] = Tg[0]; g_tx[i] = tx; g_ty[i] = ty; g_tw[i] = tw; g_th[i] = th;
        const float* Tcls = T + (size_t)(b*CC + b*LCH + 5)*HWSZ + base;
        #pragma unroll
        for (int c = 0; c < NCLS; c++)
            g_tcls[i*NCLS + c] = Tcls[(size_t)c*HWSZ];
    }
}

// ---------------------------------------------------------------------------
// Kernel B: one block, 256 threads. Minimal serial region (relevant grids
// only, bitmask ops), everything else parallel on staged data.
// ---------------------------------------------------------------------------
__global__ void kB(const int* __restrict__ G, float* __restrict__ out) {
    __shared__ int    sB[NOBJ], sG[NOBJ], sH[NOBJ], sW[NOBJ];
    __shared__ int    sCand[NOBJ], sSel[NOBJ], sDKey[NOBJ];
    __shared__ int    sMask[BB*NBA*NBA];
    __shared__ int    sDepKey[NOBJ], sDepJ[NOBJ];
    __shared__ int    sXYKey[NOBJ], sXYJ[NOBJ];
    __shared__ int    sRelList[NOBJ];
    __shared__ int    cntDep, cntXY;
    __shared__ int    warpCnt[8], warpBase[8];
    __shared__ float  sRed[4][8];
    __shared__ double sDAll[8];
    int tid = threadIdx.x;
    int lane = tid & 31, wd = tid >> 5;

    if (tid == 0) { cntDep = 0; cntXY = 0; }
    int b = G[tid*4+0], g = G[tid*4+1], h = G[tid*4+2], w = G[tid*4+3];
    sB[tid] = b; sG[tid] = g; sH[tid] = h; sW[tid] = w;
    for (int k = tid; k < BB*NBA*NBA; k += 256) sMask[k] = 0;

    // Dense-reduction partial sum (720 slots)
    double dsum = 0.0;
    for (int k = tid; k < NRED; k += 256) dsum += (double)g_part[k];
    #pragma unroll
    for (int o = 16; o; o >>= 1) dsum += __shfl_down_sync(0xffffffffu, dsum, o);
    if (lane == 0) sDAll[wd] = dsum;

    // Candidate bitmask + independent result
    int cand = 0;
    #pragma unroll
    for (int a = 1; a < NBA; a++)
        if (g_iou[tid*NBA + a] > 0.0f) cand |= (1 << a);
    sCand[tid] = cand;
    int indep = cand ? (__ffs(cand) - 1) : 0;
    sSel[tid] = indep;                       // default; serial pass overwrites relevant

    // Dependent grids (read-row writable): append read key (b,h,w)
    int dep = (w < NBA);
    if (dep) {
        int p = atomicAdd(&cntDep, 1);
        sDepKey[p] = (b << 16) | (h << 8) | w;
        sDepJ[p]   = tid;
    }
    // sel_xy sources: grids with w == h
    if (w == h) {
        int p = atomicAdd(&cntXY, 1);
        sXYKey[p] = (b << 16) | (g << 8) | h;
        sXYJ[p]   = tid;
    }
    __syncthreads();

    // Relevance: dep, or write-row (b,g,h) read by a LATER dependent grid
    int wkey = (b << 16) | (g << 8) | h;
    int rel = dep;
    int nd = cntDep;
    for (int t = 0; t < nd; t++)
        if (sDepKey[t] == wkey && sDepJ[t] > tid) rel = 1;

    // Ordered compaction of relevant indices (warp ballot)
    unsigned bal = __ballot_sync(0xffffffffu, rel);
    if (lane == 0) warpCnt[wd] = __popc(bal);
    __syncthreads();
    if (tid == 0) {
        int acc = 0;
        #pragma unroll
        for (int k = 0; k < 8; k++) { warpBase[k] = acc; acc += warpCnt[k]; }
        warpCnt[0] = acc;                    // total count reused
    }
    __syncthreads();
    int nRel = warpCnt[0];
    if (rel) sRelList[warpBase[wd] + __popc(bal & ((1u << lane) - 1u))] = tid;
    __syncthreads();

    // Tiny serial pass (thread 0) over relevant grids only
    if (tid == 0) {
        for (int t = 0; t < nRel; t++) {
            int i  = sRelList[t];
            int bi = sB[i], gi = sG[i], hi = sH[i], wi = sW[i];
            int res;
            if (wi < NBA) {
                int m = sCand[i] & ~sMask[(bi*NBA + hi)*NBA + wi];
                res = m ? (__ffs(m) - 1) : 0;
            } else {
                res = sSel[i];               // == indep
            }
            if (res) sMask[(bi*NBA + gi)*NBA + hi] |= (1 << res);
            sSel[i] = res;
        }
    }
    __syncthreads();

    // sel_xy: unique grid with (b,g,h, w==h) matching (b,g,h)
    int sxy = 0;
    int nxy = cntXY;
    for (int t = 0; t < nxy; t++)
        if (sXYKey[t] == wkey) sxy = sSel[sXYJ[t]];

    int sel = sSel[tid];
    sDKey[tid] = ((((b*HH) + h)*WW + w) << 4) | sel;   // dedup key
    __syncthreads();

    // Per-grid loss terms from staged data
    int ib = tid*NBA;
    float tx = g_tx[tid], ty = g_ty[tid], tw = g_tw[tid], th = g_th[tid];
    float tc = g_tc[tid];
    float px = g_px[ib + sxy], py = g_py[ib + sxy];
    float pc = g_pc[ib + sel], pw = g_pw[ib + sel], ph = g_ph[ib + sel];

    float xl = (tx - px) * (tx - px);
    float yl = (ty - py) * (ty - py);
    float swt = sqrtf(fmaxf(tw, 0.0f)), swp = sqrtf(fmaxf(pw, 0.0f));
    float sht = sqrtf(fmaxf(th, 0.0f)), shp = sqrtf(fmaxf(ph, 0.0f));
    float loc  = xl + yl + (swt - swp)*(swt - swp) + (sht - shp)*(sht - shp);
    float cobj = (tc - pc) * (tc - pc);

    float cls = 0.0f;
    #pragma unroll
    for (int c = 0; c < NCLS; c++) {
        float d = g_pcls[(ib + sel)*NCLS + c] - g_tcls[tid*NCLS + c];
        cls += d * d;
    }
    cls *= (1.0f / NCLS);

    // conf_nothing correction (dedup: first occurrence in scan order wins)
    float tcs = g_tconf[ib + sel];
    float corr = (tcs - pc) * (tcs - pc);
    int mykey = sDKey[tid];
    for (int j = 0; j < tid; j++)
        if (sDKey[j] == mykey) { corr = 0.0f; break; }

    float v0 = loc, v1 = cobj, v2 = cls, v3 = corr;
    #pragma unroll
    for (int o = 16; o; o >>= 1) {
        v0 += __shfl_down_sync(0xffffffffu, v0, o);
        v1 += __shfl_down_sync(0xffffffffu, v1, o);
        v2 += __shfl_down_sync(0xffffffffu, v2, o);
        v3 += __shfl_down_sync(0xffffffffu, v3, o);
    }
    if (lane == 0) { sRed[0][wd] = v0; sRed[1][wd] = v1; sRed[2][wd] = v2; sRed[3][wd] = v3; }
    __syncthreads();
    if (tid == 0) {
        float L = 0, Cq = 0, Cl = 0, Co = 0;
        double all = 0.0;
        #pragma unroll
        for (int k = 0; k < 8; k++) {
            L += sRed[0][k]; Cq += sRed[1][k]; Cl += sRed[2][k]; Co += sRed[3][k];
            all += sDAll[k];
        }
        double nothing = (all - (double)Co) / (double)TOTAL;
        out[0] = 7.0f * (L / NOBJ) + 5.0f * (Cq / NOBJ)
               + 5.0f * (float)nothing + (Cl / NOBJ);
    }
}

extern "C" void kernel_launch(void* const* d_in, const int* in_sizes, int n_in,
                              void* d_out, int out_size) {
    const float* P = (const float*)d_in[0];
    const float* T = (const float*)d_in[1];
    const int*   G = (const int*)d_in[2];
    float* out = (float*)d_out;

    kA<<<NRED + NIOU, 256>>>(P, T, G);
    kB<<<1, 256>>>(G, out);
}

// round 5
// speedup vs baseline: 5.1053x; 1.5023x over previous
#include <cuda_runtime.h>
#include <math.h>

#define NBA 10
#define NCLS 14
#define LCH 19
#define NOBJ 256
#define BB 8
#define HH 96
#define WW 96
#define CC (NBA*LCH)          // 190
#define HWSZ (HH*WW)          // 9216
#define TOTAL (BB*NBA*HH*WW)  // 737280
#define NRED 720              // reduce blocks (720*256*4 == TOTAL)
#define NIOU 10               // gather blocks (10*256 == NOBJ*NBA)
#define HSZ 1024              // dedup hash slots (power of two)

// Staging (rewritten every replay -> deterministic, no zeroing needed)
__device__ float g_part[NRED];
__device__ float g_iou  [NOBJ*NBA];
__device__ float g_pc   [NOBJ*NBA];
__device__ float g_px   [NOBJ*NBA];
__device__ float g_py   [NOBJ*NBA];
__device__ float g_pw   [NOBJ*NBA];
__device__ float g_ph   [NOBJ*NBA];
__device__ float g_tconf[NOBJ*NBA];           // T conf at channel a*LCH
__device__ float g_pcls [NOBJ*NBA*NCLS];      // pred class vals per anchor
__device__ float g_tc[NOBJ], g_tx[NOBJ], g_ty[NOBJ], g_tw[NOBJ], g_th[NOBJ];
__device__ float g_tcls [NOBJ*NCLS];          // target class (bug-preserved chan b*LCH+5)

// ---------------------------------------------------------------------------
// Kernel A: blocks [0,720) dense (tc-pc)^2 reduction; blocks [720,730) do the
// per-(grid,anchor) IoU AND stage every gather value the finalize kernel needs.
// ---------------------------------------------------------------------------
__global__ void kA(const float* __restrict__ P, const float* __restrict__ T,
                   const int* __restrict__ G) {
    int bid = blockIdx.x, tid = threadIdx.x;

    if (bid < NRED) {
        int idx = bid * 256 + tid;            // 0 .. TOTAL/4-1
        int plane = idx / (HWSZ/4);
        int off   = idx % (HWSZ/4);
        int b = plane / NBA, a = plane % NBA;
        size_t base = (size_t)(b*CC + a*LCH) * HWSZ + (size_t)off * 4;
        float4 t = *reinterpret_cast<const float4*>(T + base);
        float4 p = *reinterpret_cast<const float4*>(P + base);
        float dx = t.x - p.x, dy = t.y - p.y, dz = t.z - p.z, dw = t.w - p.w;
        float s = dx*dx + dy*dy + dz*dz + dw*dw;
        #pragma unroll
        for (int o = 16; o; o >>= 1) s += __shfl_down_sync(0xffffffffu, s, o);
        __shared__ float ws[8];
        int lane = tid & 31, wd = tid >> 5;
        if (lane == 0) ws[wd] = s;
        __syncthreads();
        if (tid == 0) {
            float bs = 0.0f;
            #pragma unroll
            for (int k = 0; k < 8; k++) bs += ws[k];
            g_part[bid] = bs;
        }
        return;
    }

    // ---- gather/IoU path ----
    int idx = (bid - NRED) * 256 + tid;       // 0 .. 2559
    int i = idx / NBA, a = idx % NBA;
    int b = G[i*4+0], g = G[i*4+1], h = G[i*4+2], w = G[i*4+3];
    int base = h * WW + w;

    const float* Tg = T + (size_t)(b*CC + g*LCH)*HWSZ + base;
    float tx = Tg[1*HWSZ], ty = Tg[2*HWSZ], tw = Tg[3*HWSZ], th = Tg[4*HWSZ];

    const float* Pa = P + (size_t)(b*CC + a*LCH)*HWSZ + base;
    float pc = Pa[0];
    float px = Pa[1*HWSZ], py = Pa[2*HWSZ], pw = Pa[3*HWSZ], ph = Pa[4*HWSZ];

    // IoU of corner boxes
    float tx1 = tx - tw*0.5f, ty1 = ty - th*0.5f, tx2 = tx + tw*0.5f, ty2 = ty + th*0.5f;
    float px1 = px - pw*0.5f, py1 = py - ph*0.5f, px2 = px + pw*0.5f, py2 = py + ph*0.5f;
    float x1 = fmaxf(tx1, px1), y1 = fmaxf(ty1, py1);
    float x2 = fminf(tx2, px2), y2 = fminf(ty2, py2);
    float inter = fmaxf(x2 - x1, 0.0f) * fmaxf(y2 - y1, 0.0f);
    float a1 = fabsf((tx2 - tx1) * (ty2 - ty1));
    float a2 = fabsf((px2 - px1) * (py2 - py1));
    g_iou[idx] = inter / (a1 + a2 - inter + 1e-6f);

    g_pc[idx] = pc; g_px[idx] = px; g_py[idx] = py; g_pw[idx] = pw; g_ph[idx] = ph;
    g_tconf[idx] = T[(size_t)(b*CC + a*LCH)*HWSZ + base];
    #pragma unroll
    for (int c = 0; c < NCLS; c++)
        g_pcls[idx*NCLS + c] = Pa[(size_t)(5 + c)*HWSZ];

    if (a == 0) {
        g_tc[i] = Tg[0]; g_tx[i] = tx; g_ty[i] = ty; g_tw[i] = tw; g_th[i] = th;
        const float* Tcls = T + (size_t)(b*CC + b*LCH + 5)*HWSZ + base;
        #pragma unroll
        for (int c = 0; c < NCLS; c++)
            g_tcls[i*NCLS + c] = Tcls[(size_t)c*HWSZ];
    }
}

// ---------------------------------------------------------------------------
// Kernel B: one block, 256 threads. Tiny serial region, hash-based dedup,
// everything else parallel on staged data.
// ---------------------------------------------------------------------------
__global__ void kB(const int* __restrict__ G, float* __restrict__ out) {
    __shared__ int    sB[NOBJ], sG[NOBJ], sH[NOBJ], sW[NOBJ];
    __shared__ int    sCand[NOBJ], sSel[NOBJ];
    __shared__ int    sMask[BB*NBA*NBA];
    __shared__ int    sDepKey[NOBJ], sDepJ[NOBJ];
    __shared__ int    sXYKey[NOBJ], sXYJ[NOBJ];
    __shared__ int    sRelList[NOBJ];
    __shared__ int    cntDep, cntXY;
    __shared__ int    warpCnt[8], warpBase[8];
    __shared__ int    tblKey[HSZ], tblMin[HSZ];
    __shared__ float  sRed[4][8];
    __shared__ double sDAll[8];
    int tid = threadIdx.x;
    int lane = tid & 31, wd = tid >> 5;

    if (tid == 0) { cntDep = 0; cntXY = 0; }
    int b = G[tid*4+0], g = G[tid*4+1], h = G[tid*4+2], w = G[tid*4+3];
    sB[tid] = b; sG[tid] = g; sH[tid] = h; sW[tid] = w;
    for (int k = tid; k < BB*NBA*NBA; k += 256) sMask[k] = 0;
    #pragma unroll
    for (int k = 0; k < HSZ/256; k++) {
        tblKey[tid + k*256] = -1;
        tblMin[tid + k*256] = 0x7fffffff;
    }

    // Dense-reduction partial sum (720 slots)
    double dsum = 0.0;
    for (int k = tid; k < NRED; k += 256) dsum += (double)g_part[k];
    #pragma unroll
    for (int o = 16; o; o >>= 1) dsum += __shfl_down_sync(0xffffffffu, dsum, o);
    if (lane == 0) sDAll[wd] = dsum;

    // Candidate bitmask + independent result
    int cand = 0;
    #pragma unroll
    for (int a = 1; a < NBA; a++)
        if (g_iou[tid*NBA + a] > 0.0f) cand |= (1 << a);
    sCand[tid] = cand;
    sSel[tid] = cand ? (__ffs(cand) - 1) : 0;   // default; serial pass overwrites relevant

    // Dependent grids (read-row writable): append read key (b,h,w)
    int dep = (w < NBA);
    if (dep) {
        int p = atomicAdd(&cntDep, 1);
        sDepKey[p] = (b << 16) | (h << 8) | w;
        sDepJ[p]   = tid;
    }
    // sel_xy sources: grids with w == h
    if (w == h) {
        int p = atomicAdd(&cntXY, 1);
        sXYKey[p] = (b << 16) | (g << 8) | h;
        sXYJ[p]   = tid;
    }
    __syncthreads();

    // Relevance: dep, or write-row (b,g,h) read by a LATER dependent grid
    int wkey = (b << 16) | (g << 8) | h;
    int rel = dep;
    int nd = cntDep;
    for (int t = 0; t < nd; t++)
        if (sDepKey[t] == wkey && sDepJ[t] > tid) rel = 1;

    // Ordered compaction of relevant indices (warp ballot)
    unsigned bal = __ballot_sync(0xffffffffu, rel);
    if (lane == 0) warpCnt[wd] = __popc(bal);
    __syncthreads();
    if (tid == 0) {
        int acc = 0;
        #pragma unroll
        for (int k = 0; k < 8; k++) { warpBase[k] = acc; acc += warpCnt[k]; }
        warpCnt[0] = acc;                    // total count reused
    }
    __syncthreads();
    int nRel = warpCnt[0];
    if (rel) sRelList[warpBase[wd] + __popc(bal & ((1u << lane) - 1u))] = tid;
    __syncthreads();

    // Tiny serial pass (thread 0) over relevant grids only
    if (tid == 0) {
        for (int t = 0; t < nRel; t++) {
            int i  = sRelList[t];
            int bi = sB[i], gi = sG[i], hi = sH[i], wi = sW[i];
            int res;
            if (wi < NBA) {
                int m = sCand[i] & ~sMask[(bi*NBA + hi)*NBA + wi];
                res = m ? (__ffs(m) - 1) : 0;
            } else {
                res = sSel[i];               // == indep
            }
            if (res) sMask[(bi*NBA + gi)*NBA + hi] |= (1 << res);
            sSel[i] = res;
        }
    }
    __syncthreads();

    // sel_xy: unique grid with (b,g,h, w==h) matching (b,g,h)
    int sxy = 0;
    int nxy = cntXY;
    for (int t = 0; t < nxy; t++)
        if (sXYKey[t] == wkey) sxy = sSel[sXYJ[t]];

    int sel = sSel[tid];

    // Dedup via linear-probing hash: first occurrence (min tid) per key wins.
    // Key fits 21 bits; placement order-independence: probing for a key always
    // finds it before any empty slot, regardless of concurrent insert order.
    int dkey = ((((b*HH) + h)*WW + w) << 4) | sel;
    int slot = (dkey * 0x9E3779B1u) >> 22;   // 10-bit hash
    while (true) {
        int prev = atomicCAS(&tblKey[slot], -1, dkey);
        if (prev == -1 || prev == dkey) { atomicMin(&tblMin[slot], tid); break; }
        slot = (slot + 1) & (HSZ - 1);
    }
    __syncthreads();
    // Query own key
    int isFirst;
    {
        int s2 = (dkey * 0x9E3779B1u) >> 22;
        while (tblKey[s2] != dkey) s2 = (s2 + 1) & (HSZ - 1);
        isFirst = (tblMin[s2] == tid);
    }

    // Per-grid loss terms from staged data
    int ib = tid*NBA;
    float tx = g_tx[tid], ty = g_ty[tid], tw = g_tw[tid], th = g_th[tid];
    float tc = g_tc[tid];
    float px = g_px[ib + sxy], py = g_py[ib + sxy];
    float pc = g_pc[ib + sel], pw = g_pw[ib + sel], ph = g_ph[ib + sel];

    float xl = (tx - px) * (tx - px);
    float yl = (ty - py) * (ty - py);
    float swt = sqrtf(fmaxf(tw, 0.0f)), swp = sqrtf(fmaxf(pw, 0.0f));
    float sht = sqrtf(fmaxf(th, 0.0f)), shp = sqrtf(fmaxf(ph, 0.0f));
    float loc  = xl + yl + (swt - swp)*(swt - swp) + (sht - shp)*(sht - shp);
    float cobj = (tc - pc) * (tc - pc);

    float cls = 0.0f;
    #pragma unroll
    for (int c = 0; c < NCLS; c++) {
        float d = g_pcls[(ib + sel)*NCLS + c] - g_tcls[tid*NCLS + c];
        cls += d * d;
    }
    cls *= (1.0f / NCLS);

    // conf_nothing correction at distinct zeroed positions
    float tcs = g_tconf[ib + sel];
    float corr = isFirst ? (tcs - pc) * (tcs - pc) : 0.0f;

    float v0 = loc, v1 = cobj, v2 = cls, v3 = corr;
    #pragma unroll
    for (int o = 16; o; o >>= 1) {
        v0 += __shfl_down_sync(0xffffffffu, v0, o);
        v1 += __shfl_down_sync(0xffffffffu, v1, o);
        v2 += __shfl_down_sync(0xffffffffu, v2, o);
        v3 += __shfl_down_sync(0xffffffffu, v3, o);
    }
    if (lane == 0) { sRed[0][wd] = v0; sRed[1][wd] = v1; sRed[2][wd] = v2; sRed[3][wd] = v3; }
    __syncthreads();
    if (tid == 0) {
        float L = 0, Cq = 0, Cl = 0, Co = 0;
        double all = 0.0;
        #pragma unroll
        for (int k = 0; k < 8; k++) {
            L += sRed[0][k]; Cq += sRed[1][k]; Cl += sRed[2][k]; Co += sRed[3][k];
            all += sDAll[k];
        }
        double nothing = (all - (double)Co) / (double)TOTAL;
        out[0] = 7.0f * (L / NOBJ) + 5.0f * (Cq / NOBJ)
               + 5.0f * (float)nothing + (Cl / NOBJ);
    }
}

extern "C" void kernel_launch(void* const* d_in, const int* in_sizes, int n_in,
                              void* d_out, int out_size) {
    const float* P = (const float*)d_in[0];
    const float* T = (const float*)d_in[1];
    const int*   G = (const int*)d_in[2];
    float* out = (float*)d_out;

    kA<<<NRED + NIOU, 256>>>(P, T, G);
    kB<<<1, 256>>>(G, out);
}

// round 6
// speedup vs baseline: 5.5826x; 1.0935x over previous
#include <cuda_runtime.h>
#include <math.h>

#define NBA 10
#define NCLS 14
#define LCH 19
#define NOBJ 256
#define BB 8
#define HH 96
#define WW 96
#define CC (NBA*LCH)          // 190
#define HWSZ (HH*WW)          // 9216
#define TOTAL (BB*NBA*HH*WW)  // 737280
#define NRED 720              // reduce blocks (720*256*4 == TOTAL)
#define NIOU 10               // gather blocks (10*256 == NOBJ*NBA)
#define NBLK (NRED + NIOU)
#define HSZ 1024              // dedup hash slots (power of two)

// Staging (rewritten every replay -> deterministic, no zeroing needed)
__device__ float g_part[NRED];
__device__ float g_iou[NOBJ*NBA];
__device__ float g_A1 [NOBJ*NBA];   // (tx-px)^2 + (ty-py)^2
__device__ float g_A2 [NOBJ*NBA];   // (sqrt tw - sqrt pw)^2 + (sqrt th - sqrt ph)^2
__device__ float g_A3 [NOBJ*NBA];   // (tc - pc)^2
__device__ float g_A4 [NOBJ*NBA];   // mean_c (pcls - tcls)^2
__device__ float g_A5 [NOBJ*NBA];   // (tconf_a - pc)^2
__device__ int   g_ticket;          // starts 0; finalizer resets to 0 each replay

__global__ void kFused(const float* __restrict__ P, const float* __restrict__ T,
                       const int* __restrict__ G, float* __restrict__ out) {
    int bid = blockIdx.x, tid = threadIdx.x;
    int lane = tid & 31, wd = tid >> 5;

    // ---------------- Phase 1: staging work ----------------
    if (bid < NRED) {
        // dense (tc-pc)^2 reduction
        int idx = bid * 256 + tid;            // 0 .. TOTAL/4-1
        int plane = idx / (HWSZ/4);
        int off   = idx % (HWSZ/4);
        int b = plane / NBA, a = plane % NBA;
        size_t base = (size_t)(b*CC + a*LCH) * HWSZ + (size_t)off * 4;
        float4 t = *reinterpret_cast<const float4*>(T + base);
        float4 p = *reinterpret_cast<const float4*>(P + base);
        float dx = t.x - p.x, dy = t.y - p.y, dz = t.z - p.z, dw = t.w - p.w;
        float s = dx*dx + dy*dy + dz*dz + dw*dw;
        #pragma unroll
        for (int o = 16; o; o >>= 1) s += __shfl_down_sync(0xffffffffu, s, o);
        __shared__ float ws[8];
        if (lane == 0) ws[wd] = s;
        __syncthreads();
        if (tid == 0) {
            float bs = 0.0f;
            #pragma unroll
            for (int k = 0; k < 8; k++) bs += ws[k];
            g_part[bid] = bs;
        }
    } else {
        // gather/IoU/loss-term staging
        int idx = (bid - NRED) * 256 + tid;   // 0 .. 2559
        int i = idx / NBA, a = idx % NBA;
        int b = G[i*4+0], g = G[i*4+1], h = G[i*4+2], w = G[i*4+3];
        int base = h * WW + w;

        const float* Tg = T + (size_t)(b*CC + g*LCH)*HWSZ + base;
        float tc = Tg[0];
        float tx = Tg[1*HWSZ], ty = Tg[2*HWSZ], tw = Tg[3*HWSZ], th = Tg[4*HWSZ];

        const float* Pa = P + (size_t)(b*CC + a*LCH)*HWSZ + base;
        float pc = Pa[0];
        float px = Pa[1*HWSZ], py = Pa[2*HWSZ], pw = Pa[3*HWSZ], ph = Pa[4*HWSZ];

        // IoU of corner boxes
        float tx1 = tx - tw*0.5f, ty1 = ty - th*0.5f, tx2 = tx + tw*0.5f, ty2 = ty + th*0.5f;
        float px1 = px - pw*0.5f, py1 = py - ph*0.5f, px2 = px + pw*0.5f, py2 = py + ph*0.5f;
        float x1 = fmaxf(tx1, px1), y1 = fmaxf(ty1, py1);
        float x2 = fminf(tx2, px2), y2 = fminf(ty2, py2);
        float inter = fmaxf(x2 - x1, 0.0f) * fmaxf(y2 - y1, 0.0f);
        float a1 = fabsf((tx2 - tx1) * (ty2 - ty1));
        float a2 = fabsf((px2 - px1) * (py2 - py1));
        g_iou[idx] = inter / (a1 + a2 - inter + 1e-6f);

        g_A1[idx] = (tx - px)*(tx - px) + (ty - py)*(ty - py);
        float swt = sqrtf(fmaxf(tw, 0.0f)), swp = sqrtf(fmaxf(pw, 0.0f));
        float sht = sqrtf(fmaxf(th, 0.0f)), shp = sqrtf(fmaxf(ph, 0.0f));
        g_A2[idx] = (swt - swp)*(swt - swp) + (sht - shp)*(sht - shp);
        g_A3[idx] = (tc - pc)*(tc - pc);

        const float* Tcls = T + (size_t)(b*CC + b*LCH + 5)*HWSZ + base;  // bug-preserved
        float cls = 0.0f;
        #pragma unroll
        for (int c = 0; c < NCLS; c++) {
            float d = Pa[(size_t)(5 + c)*HWSZ] - Tcls[(size_t)c*HWSZ];
            cls += d * d;
        }
        g_A4[idx] = cls * (1.0f / NCLS);

        float tcs = T[(size_t)(b*CC + a*LCH)*HWSZ + base];
        g_A5[idx] = (tcs - pc)*(tcs - pc);
    }

    // ---------------- Ticket: last block finalizes ----------------
    __shared__ int sIsLast;
    __syncthreads();
    __threadfence();
    if (tid == 0) {
        int t = atomicAdd(&g_ticket, 1);
        sIsLast = (t == NBLK - 1);
    }
    __syncthreads();
    if (!sIsLast) return;
    __threadfence();   // acquire: order staged-data reads after the ticket

    // ---------------- Phase 2: finalize (one block, 256 threads) ----------------
    __shared__ int    sB[NOBJ], sG[NOBJ], sH[NOBJ], sW[NOBJ];
    __shared__ int    sCand[NOBJ], sSel[NOBJ];
    __shared__ int    sMask[BB*NBA*NBA];
    __shared__ int    sDepKey[NOBJ], sDepJ[NOBJ];
    __shared__ int    sXYKey[NOBJ], sXYJ[NOBJ];
    __shared__ int    sRelList[NOBJ];
    __shared__ int    cntDep, cntXY;
    __shared__ int    warpCnt[8], warpBase[8];
    __shared__ int    tblKey[HSZ], tblMin[HSZ];
    __shared__ float  sRed[4][8];
    __shared__ double sDAll[8];

    if (tid == 0) { cntDep = 0; cntXY = 0; }
    int b = G[tid*4+0], g = G[tid*4+1], h = G[tid*4+2], w = G[tid*4+3];
    sB[tid] = b; sG[tid] = g; sH[tid] = h; sW[tid] = w;
    for (int k = tid; k < BB*NBA*NBA; k += 256) sMask[k] = 0;
    #pragma unroll
    for (int k = 0; k < HSZ/256; k++) {
        tblKey[tid + k*256] = -1;
        tblMin[tid + k*256] = 0x7fffffff;
    }

    // Dense-reduction partial sum (720 slots)
    double dsum = 0.0;
    for (int k = tid; k < NRED; k += 256) dsum += (double)g_part[k];
    #pragma unroll
    for (int o = 16; o; o >>= 1) dsum += __shfl_down_sync(0xffffffffu, dsum, o);
    if (lane == 0) sDAll[wd] = dsum;

    // Candidate bitmask + independent result
    int cand = 0;
    #pragma unroll
    for (int a = 1; a < NBA; a++)
        if (g_iou[tid*NBA + a] > 0.0f) cand |= (1 << a);
    sCand[tid] = cand;
    sSel[tid] = cand ? (__ffs(cand) - 1) : 0;   // default; serial pass overwrites relevant

    // Dependent grids (read-row writable): append read key (b,h,w)
    int dep = (w < NBA);
    if (dep) {
        int p = atomicAdd(&cntDep, 1);
        sDepKey[p] = (b << 16) | (h << 8) | w;
        sDepJ[p]   = tid;
    }
    // sel_xy sources: grids with w == h
    if (w == h) {
        int p = atomicAdd(&cntXY, 1);
        sXYKey[p] = (b << 16) | (g << 8) | h;
        sXYJ[p]   = tid;
    }
    __syncthreads();

    // Relevance: dep, or write-row (b,g,h) read by a LATER dependent grid
    int wkey = (b << 16) | (g << 8) | h;
    int rel = dep;
    int nd = cntDep;
    for (int t = 0; t < nd; t++)
        if (sDepKey[t] == wkey && sDepJ[t] > tid) rel = 1;

    // Ordered compaction of relevant indices (warp ballot)
    unsigned bal = __ballot_sync(0xffffffffu, rel);
    if (lane == 0) warpCnt[wd] = __popc(bal);
    __syncthreads();
    if (tid == 0) {
        int acc = 0;
        #pragma unroll
        for (int k = 0; k < 8; k++) { warpBase[k] = acc; acc += warpCnt[k]; }
        warpCnt[0] = acc;
    }
    __syncthreads();
    int nRel = warpCnt[0];
    if (rel) sRelList[warpBase[wd] + __popc(bal & ((1u << lane) - 1u))] = tid;
    __syncthreads();

    // Tiny serial pass (thread 0) over relevant grids only
    if (tid == 0) {
        for (int t = 0; t < nRel; t++) {
            int i  = sRelList[t];
            int bi = sB[i], gi = sG[i], hi = sH[i], wi = sW[i];
            int res;
            if (wi < NBA) {
                int m = sCand[i] & ~sMask[(bi*NBA + hi)*NBA + wi];
                res = m ? (__ffs(m) - 1) : 0;
            } else {
                res = sSel[i];
            }
            if (res) sMask[(bi*NBA + gi)*NBA + hi] |= (1 << res);
            sSel[i] = res;
        }
    }
    __syncthreads();

    // sel_xy: unique grid with (b,g,h, w==h) matching (b,g,h)
    int sxy = 0;
    int nxy = cntXY;
    for (int t = 0; t < nxy; t++)
        if (sXYKey[t] == wkey) sxy = sSel[sXYJ[t]];

    int sel = sSel[tid];

    // Dedup via linear-probing hash: first occurrence (min tid) per key wins.
    int dkey = ((((b*HH) + h)*WW + w) << 4) | sel;
    int slot = (int)(((unsigned)dkey * 0x9E3779B1u) >> 22);
    while (true) {
        int prev = atomicCAS(&tblKey[slot], -1, dkey);
        if (prev == -1 || prev == dkey) { atomicMin(&tblMin[slot], tid); break; }
        slot = (slot + 1) & (HSZ - 1);
    }
    __syncthreads();
    int isFirst;
    {
        int s2 = (int)(((unsigned)dkey * 0x9E3779B1u) >> 22);
        while (tblKey[s2] != dkey) s2 = (s2 + 1) & (HSZ - 1);
        isFirst = (tblMin[s2] == tid);
    }

    // Loss terms: 5 staged loads
    int ib = tid*NBA;
    float loc  = g_A1[ib + sxy] + g_A2[ib + sel];
    float cobj = g_A3[ib + sel];
    float cls  = g_A4[ib + sel];
    float corr = isFirst ? g_A5[ib + sel] : 0.0f;

    float v0 = loc, v1 = cobj, v2 = cls, v3 = corr;
    #pragma unroll
    for (int o = 16; o; o >>= 1) {
        v0 += __shfl_down_sync(0xffffffffu, v0, o);
        v1 += __shfl_down_sync(0xffffffffu, v1, o);
        v2 += __shfl_down_sync(0xffffffffu, v2, o);
        v3 += __shfl_down_sync(0xffffffffu, v3, o);
    }
    if (lane == 0) { sRed[0][wd] = v0; sRed[1][wd] = v1; sRed[2][wd] = v2; sRed[3][wd] = v3; }
    __syncthreads();
    if (tid == 0) {
        float L = 0, Cq = 0, Cl = 0, Co = 0;
        double all = 0.0;
        #pragma unroll
        for (int k = 0; k < 8; k++) {
            L += sRed[0][k]; Cq += sRed[1][k]; Cl += sRed[2][k]; Co += sRed[3][k];
            all += sDAll[k];
        }
        double nothing = (all - (double)Co) / (double)TOTAL;
        out[0] = 7.0f * (L / NOBJ) + 5.0f * (Cq / NOBJ)
               + 5.0f * (float)nothing + (Cl / NOBJ);
        g_ticket = 0;   // reset for next graph replay (deterministic)
    }
}

extern "C" void kernel_launch(void* const* d_in, const int* in_sizes, int n_in,
                              void* d_out, int out_size) {
    const float* P = (const float*)d_in[0];
    const float* T = (const float*)d_in[1];
    const int*   G = (const int*)d_in[2];
    float* out = (float*)d_out;

    kFused<<<NBLK, 256>>>(P, T, G, out);
}

// round 8
// speedup vs baseline: 6.2388x; 1.1175x over previous
#include <cuda_runtime.h>
#include <math.h>

#define NBA 10
#define NCLS 14
#define LCH 19
#define NOBJ 256
#define BB 8
#define HH 96
#define WW 96
#define CC (NBA*LCH)          // 190
#define HWSZ (HH*WW)          // 9216
#define TOTAL (BB*NBA*HH*WW)  // 737280
#define NF4 (TOTAL/4)         // 184320 float4 per tensor
#define UNR 8                 // float4 pairs per thread
#define NRED 90               // reduce blocks: 90*256*8 == NF4
#define NIOU 10               // gather blocks (10*256 == NOBJ*NBA)
#define NBLK (NRED + NIOU)    // 100 blocks -> single wave
#define HSZ 1024              // dedup hash slots (power of two)

// Staging (rewritten every replay -> deterministic, no zeroing needed)
__device__ float g_part[NRED];
__device__ float g_iou[NOBJ*NBA];
__device__ float g_A1 [NOBJ*NBA];   // (tx-px)^2 + (ty-py)^2
__device__ float g_A2 [NOBJ*NBA];   // (sqrt tw - sqrt pw)^2 + (sqrt th - sqrt ph)^2
__device__ float g_A3 [NOBJ*NBA];   // (tc - pc)^2
__device__ float g_A4 [NOBJ*NBA];   // mean_c (pcls - tcls)^2
__device__ float g_A5 [NOBJ*NBA];   // (tconf_a - pc)^2
__device__ int   g_ticket;          // starts 0; finalizer resets to 0 each replay

__global__ void kFused(const float* __restrict__ P, const float* __restrict__ T,
                       const int* __restrict__ G, float* __restrict__ out) {
    int bid = blockIdx.x, tid = threadIdx.x;
    int lane = tid & 31, wd = tid >> 5;

    // ---------------- Phase 1: staging work ----------------
    if (bid < NRED) {
        // dense (tc-pc)^2 reduction, 8 float4-pairs per thread (MLP=16)
        float s = 0.0f;
        int base_idx = bid * (256*UNR) + tid;
        #pragma unroll
        for (int k = 0; k < UNR; k++) {
            int fidx = base_idx + k * 256;            // float4 index
            int plane = fidx / (HWSZ/4);
            int off   = fidx % (HWSZ/4);
            int b = plane / NBA, a = plane % NBA;
            size_t base = (size_t)(b*CC + a*LCH) * HWSZ + (size_t)off * 4;
            float4 t = *reinterpret_cast<const float4*>(T + base);
            float4 p = *reinterpret_cast<const float4*>(P + base);
            float dx = t.x - p.x, dy = t.y - p.y, dz = t.z - p.z, dw = t.w - p.w;
            s += dx*dx + dy*dy + dz*dz + dw*dw;
        }
        #pragma unroll
        for (int o = 16; o; o >>= 1) s += __shfl_down_sync(0xffffffffu, s, o);
        __shared__ float ws[8];
        if (lane == 0) ws[wd] = s;
        __syncthreads();
        if (tid == 0) {
            float bs = 0.0f;
            #pragma unroll
            for (int k = 0; k < 8; k++) bs += ws[k];
            g_part[bid] = bs;
        }
    } else {
        // gather/IoU/loss-term staging
        int idx = (bid - NRED) * 256 + tid;   // 0 .. 2559
        int i = idx / NBA, a = idx % NBA;
        int b = G[i*4+0], g = G[i*4+1], h = G[i*4+2], w = G[i*4+3];
        int base = h * WW + w;

        const float* Tg = T + (size_t)(b*CC + g*LCH)*HWSZ + base;
        float tc = Tg[0];
        float tx = Tg[1*HWSZ], ty = Tg[2*HWSZ], tw = Tg[3*HWSZ], th = Tg[4*HWSZ];

        const float* Pa = P + (size_t)(b*CC + a*LCH)*HWSZ + base;
        float pc = Pa[0];
        float px = Pa[1*HWSZ], py = Pa[2*HWSZ], pw = Pa[3*HWSZ], ph = Pa[4*HWSZ];

        // IoU of corner boxes
        float tx1 = tx - tw*0.5f, ty1 = ty - th*0.5f, tx2 = tx + tw*0.5f, ty2 = ty + th*0.5f;
        float px1 = px - pw*0.5f, py1 = py - ph*0.5f, px2 = px + pw*0.5f, py2 = py + ph*0.5f;
        float x1 = fmaxf(tx1, px1), y1 = fmaxf(ty1, py1);
        float x2 = fminf(tx2, px2), y2 = fminf(ty2, py2);
        float inter = fmaxf(x2 - x1, 0.0f) * fmaxf(y2 - y1, 0.0f);
        float a1 = fabsf((tx2 - tx1) * (ty2 - ty1));
        float a2 = fabsf((px2 - px1) * (py2 - py1));
        g_iou[idx] = inter / (a1 + a2 - inter + 1e-6f);

        g_A1[idx] = (tx - px)*(tx - px) + (ty - py)*(ty - py);
        float swt = sqrtf(fmaxf(tw, 0.0f)), swp = sqrtf(fmaxf(pw, 0.0f));
        float sht = sqrtf(fmaxf(th, 0.0f)), shp = sqrtf(fmaxf(ph, 0.0f));
        g_A2[idx] = (swt - swp)*(swt - swp) + (sht - shp)*(sht - shp);
        g_A3[idx] = (tc - pc)*(tc - pc);

        const float* Tcls = T + (size_t)(b*CC + b*LCH + 5)*HWSZ + base;  // bug-preserved
        float cls = 0.0f;
        #pragma unroll
        for (int c = 0; c < NCLS; c++) {
            float d = Pa[(size_t)(5 + c)*HWSZ] - Tcls[(size_t)c*HWSZ];
            cls += d * d;
        }
        g_A4[idx] = cls * (1.0f / NCLS);

        float tcs = T[(size_t)(b*CC + a*LCH)*HWSZ + base];
        g_A5[idx] = (tcs - pc)*(tcs - pc);
    }

    // ---------------- Ticket: last block finalizes ----------------
    __shared__ int sIsLast;
    __syncthreads();
    __threadfence();
    if (tid == 0) {
        int t = atomicAdd(&g_ticket, 1);
        sIsLast = (t == NBLK - 1);
    }
    __syncthreads();
    if (!sIsLast) return;
    __threadfence();   // acquire: order staged-data reads after the ticket

    // ---------------- Phase 2: finalize (one block, 256 threads) ----------------
    __shared__ int    sB[NOBJ], sG[NOBJ], sH[NOBJ], sW[NOBJ];
    __shared__ int    sCand[NOBJ], sSel[NOBJ];
    __shared__ int    sMask[BB*NBA*NBA];
    __shared__ int    sDepKey[NOBJ], sDepJ[NOBJ];
    __shared__ int    sXYKey[NOBJ], sXYJ[NOBJ];
    __shared__ int    sRelList[NOBJ];
    __shared__ int    cntDep, cntXY;
    __shared__ int    warpCnt[8], warpBase[8];
    __shared__ int    tblKey[HSZ], tblMin[HSZ];
    __shared__ float  sRed[4][8];
    __shared__ double sDAll[8];

    if (tid == 0) { cntDep = 0; cntXY = 0; }
    int b = G[tid*4+0], g = G[tid*4+1], h = G[tid*4+2], w = G[tid*4+3];
    sB[tid] = b; sG[tid] = g; sH[tid] = h; sW[tid] = w;
    for (int k = tid; k < BB*NBA*NBA; k += 256) sMask[k] = 0;
    #pragma unroll
    for (int k = 0; k < HSZ/256; k++) {
        tblKey[tid + k*256] = -1;
        tblMin[tid + k*256] = 0x7fffffff;
    }

    // Dense-reduction partial sum (90 slots, first three warps)
    double dsum = (tid < NRED) ? (double)g_part[tid] : 0.0;
    #pragma unroll
    for (int o = 16; o; o >>= 1) dsum += __shfl_down_sync(0xffffffffu, dsum, o);
    if (lane == 0) sDAll[wd] = dsum;

    // Candidate bitmask + independent result
    int cand = 0;
    #pragma unroll
    for (int a = 1; a < NBA; a++)
        if (g_iou[tid*NBA + a] > 0.0f) cand |= (1 << a);
    sCand[tid] = cand;
    sSel[tid] = cand ? (__ffs(cand) - 1) : 0;   // default; serial pass overwrites relevant

    // Dependent grids (read-row writable): append read key (b,h,w)
    int dep = (w < NBA);
    if (dep) {
        int p = atomicAdd(&cntDep, 1);
        sDepKey[p] = (b << 16) | (h << 8) | w;
        sDepJ[p]   = tid;
    }
    // sel_xy sources: grids with w == h
    if (w == h) {
        int p = atomicAdd(&cntXY, 1);
        sXYKey[p] = (b << 16) | (g << 8) | h;
        sXYJ[p]   = tid;
    }
    __syncthreads();

    // Relevance: dep, or write-row (b,g,h) read by a LATER dependent grid
    int wkey = (b << 16) | (g << 8) | h;
    int rel = dep;
    int nd = cntDep;
    for (int t = 0; t < nd; t++)
        if (sDepKey[t] == wkey && sDepJ[t] > tid) rel = 1;

    // Ordered compaction of relevant indices (warp ballot)
    unsigned bal = __ballot_sync(0xffffffffu, rel);
    if (lane == 0) warpCnt[wd] = __popc(bal);
    __syncthreads();
    if (tid == 0) {
        int acc = 0;
        #pragma unroll
        for (int k = 0; k < 8; k++) { warpBase[k] = acc; acc += warpCnt[k]; }
        warpCnt[0] = acc;
    }
    __syncthreads();
    int nRel = warpCnt[0];
    if (rel) sRelList[warpBase[wd] + __popc(bal & ((1u << lane) - 1u))] = tid;
    __syncthreads();

    // Tiny serial pass (thread 0) over relevant grids only
    if (tid == 0) {
        for (int t = 0; t < nRel; t++) {
            int i  = sRelList[t];
            int bi = sB[i], gi = sG[i], hi = sH[i], wi = sW[i];
            int res;
            if (wi < NBA) {
                int m = sCand[i] & ~sMask[(bi*NBA + hi)*NBA + wi];
                res = m ? (__ffs(m) - 1) : 0;
            } else {
                res = sSel[i];
            }
            if (res) sMask[(bi*NBA + gi)*NBA + hi] |= (1 << res);
            sSel[i] = res;
        }
    }
    __syncthreads();

    // sel_xy: unique grid with (b,g,h, w==h) matching (b,g,h)
    int sxy = 0;
    int nxy = cntXY;
    for (int t = 0; t < nxy; t++)
        if (sXYKey[t] == wkey) sxy = sSel[sXYJ[t]];

    int sel = sSel[tid];

    // Dedup via linear-probing hash: first occurrence (min tid) per key wins.
    int dkey = ((((b*HH) + h)*WW + w) << 4) | sel;
    int slot = (int)(((unsigned)dkey * 0x9E3779B1u) >> 22);
    while (true) {
        int prev = atomicCAS(&tblKey[slot], -1, dkey);
        if (prev == -1 || prev == dkey) { atomicMin(&tblMin[slot], tid); break; }
        slot = (slot + 1) & (HSZ - 1);
    }
    __syncthreads();
    int isFirst;
    {
        int s2 = (int)(((unsigned)dkey * 0x9E3779B1u) >> 22);
        while (tblKey[s2] != dkey) s2 = (s2 + 1) & (HSZ - 1);
        isFirst = (tblMin[s2] == tid);
    }

    // Loss terms: 5 staged loads
    int ib = tid*NBA;
    float loc  = g_A1[ib + sxy] + g_A2[ib + sel];
    float cobj = g_A3[ib + sel];
    float cls  = g_A4[ib + sel];
    float corr = isFirst ? g_A5[ib + sel] : 0.0f;

    float v0 = loc, v1 = cobj, v2 = cls, v3 = corr;
    #pragma unroll
    for (int o = 16; o; o >>= 1) {
        v0 += __shfl_down_sync(0xffffffffu, v0, o);
        v1 += __shfl_down_sync(0xffffffffu, v1, o);
        v2 += __shfl_down_sync(0xffffffffu, v2, o);
        v3 += __shfl_down_sync(0xffffffffu, v3, o);
    }
    if (lane == 0) { sRed[0][wd] = v0; sRed[1][wd] = v1; sRed[2][wd] = v2; sRed[3][wd] = v3; }
    __syncthreads();
    if (tid == 0) {
        float L = 0, Cq = 0, Cl = 0, Co = 0;
        double all = 0.0;
        #pragma unroll
        for (int k = 0; k < 8; k++) {
            L += sRed[0][k]; Cq += sRed[1][k]; Cl += sRed[2][k]; Co += sRed[3][k];
            all += sDAll[k];
        }
        double nothing = (all - (double)Co) / (double)TOTAL;
        out[0] = 7.0f * (L / NOBJ) + 5.0f * (Cq / NOBJ)
               + 5.0f * (float)nothing + (Cl / NOBJ);
        g_ticket = 0;   // reset for next graph replay (deterministic)
    }
}

extern "C" void kernel_launch(void* const* d_in, const int* in_sizes, int n_in,
                              void* d_out, int out_size) {
    const float* P = (const float*)d_in[0];
    const float* T = (const float*)d_in[1];
    const int*   G = (const int*)d_in[2];
    float* out = (float*)d_out;

    kFused<<<NBLK, 256>>>(P, T, G, out);
}

// round 9
// speedup vs baseline: 6.3333x; 1.0152x over previous
#include <cuda_runtime.h>
#include <math.h>

#define NBA 10
#define NCLS 14
#define LCH 19
#define NOBJ 256
#define BB 8
#define HH 96
#define WW 96
#define CC (NBA*LCH)          // 190
#define HWSZ (HH*WW)          // 9216
#define TOTAL (BB*NBA*HH*WW)  // 737280
#define NF4 (TOTAL/4)         // 184320 float4 per tensor
#define UNR 2                 // float4 pairs per thread
#define NRED 360              // reduce blocks: 360*256*2 == NF4
#define NIOU 80               // gather blocks: 80 * 32 pairs == 2560
#define NBLK (NIOU + NRED)
#define HSZ 1024              // dedup hash slots (power of two)

// Staging (rewritten every replay -> deterministic, no zeroing needed)
__device__ float g_part[NRED];
__device__ float g_iou[NOBJ*NBA];
__device__ float g_A1 [NOBJ*NBA];   // (tx-px)^2 + (ty-py)^2
__device__ float g_A2 [NOBJ*NBA];   // (sqrt tw - sqrt pw)^2 + (sqrt th - sqrt ph)^2
__device__ float g_A3 [NOBJ*NBA];   // (tc - pc)^2
__device__ float g_A4 [NOBJ*NBA];   // mean_c (pcls - tcls)^2
__device__ float g_A5 [NOBJ*NBA];   // (tconf_a - pc)^2
__device__ int   g_ticket;          // starts 0; finalizer resets to 0 each replay

__global__ void kFused(const float* __restrict__ P, const float* __restrict__ T,
                       const int* __restrict__ G, float* __restrict__ out) {
    int bid = blockIdx.x, tid = threadIdx.x;
    int lane = tid & 31, wd = tid >> 5;

    // ---------------- Phase 1: staging work ----------------
    if (bid < NIOU) {
        // gather/IoU/loss-term staging: 8 threads per (grid,anchor) pair,
        // 32 pairs per block. Each thread issues <=8 independent scattered loads.
        __shared__ float sTB[32][4], sPB[32][4], sBoxP[32][4], sCls[32][8];
        int pl   = tid >> 3;                  // pair-local 0..31
        int slot = tid & 7;
        int pp   = bid * 32 + pl;             // 0 .. 2559
        int i = pp / NBA, a = pp % NBA;
        int4 gi = ((const int4*)G)[i];
        int b = gi.x, g = gi.y, h = gi.z, w = gi.w;
        int base = h * WW + w;
        const float* Tg   = T + (size_t)(b*CC + g*LCH)*HWSZ + base;
        const float* Pa   = P + (size_t)(b*CC + a*LCH)*HWSZ + base;
        const float* Tcls = T + (size_t)(b*CC + b*LCH + 5)*HWSZ + base; // bug-preserved

        // class partial: slot handles c=slot and (if slot<6) c=slot+8
        float clsPart;
        {
            float d = Pa[(size_t)(5 + slot)*HWSZ] - Tcls[(size_t)slot*HWSZ];
            clsPart = d * d;
            if (slot < 6) {
                float d2 = Pa[(size_t)(13 + slot)*HWSZ] - Tcls[(size_t)(8 + slot)*HWSZ];
                clsPart += d2 * d2;
            }
        }
        sCls[pl][slot] = clsPart;

        if (slot < 4) {
            float tcomp = Tg[(size_t)(1 + slot)*HWSZ];
            float pcomp = Pa[(size_t)(1 + slot)*HWSZ];
            sTB[pl][slot] = tcomp; sPB[pl][slot] = pcomp;
            float bp;
            if (slot < 2) { float d = tcomp - pcomp; bp = d * d; }
            else {
                float st = sqrtf(fmaxf(tcomp, 0.0f)), sp = sqrtf(fmaxf(pcomp, 0.0f));
                float d = st - sp; bp = d * d;
            }
            sBoxP[pl][slot] = bp;
        } else if (slot == 4) {
            float pc  = Pa[0];
            float tc  = Tg[0];
            float tcs = T[(size_t)(b*CC + a*LCH)*HWSZ + base];
            g_A3[pp] = (tc - pc)*(tc - pc);
            g_A5[pp] = (tcs - pc)*(tcs - pc);
        }
        __syncthreads();
        if (slot == 0) {
            float tx = sTB[pl][0], ty = sTB[pl][1], tw = sTB[pl][2], th = sTB[pl][3];
            float px = sPB[pl][0], py = sPB[pl][1], pw = sPB[pl][2], ph = sPB[pl][3];
            float tx1 = tx - tw*0.5f, ty1 = ty - th*0.5f, tx2 = tx + tw*0.5f, ty2 = ty + th*0.5f;
            float px1 = px - pw*0.5f, py1 = py - ph*0.5f, px2 = px + pw*0.5f, py2 = py + ph*0.5f;
            float x1 = fmaxf(tx1, px1), y1 = fmaxf(ty1, py1);
            float x2 = fminf(tx2, px2), y2 = fminf(ty2, py2);
            float inter = fmaxf(x2 - x1, 0.0f) * fmaxf(y2 - y1, 0.0f);
            float a1 = fabsf((tx2 - tx1) * (ty2 - ty1));
            float a2 = fabsf((px2 - px1) * (py2 - py1));
            g_iou[pp] = inter / (a1 + a2 - inter + 1e-6f);
            g_A1[pp] = sBoxP[pl][0] + sBoxP[pl][1];
            g_A2[pp] = sBoxP[pl][2] + sBoxP[pl][3];
            float cs = 0.0f;
            #pragma unroll
            for (int k = 0; k < 8; k++) cs += sCls[pl][k];
            g_A4[pp] = cs * (1.0f / NCLS);
        }
    } else {
        // dense (tc-pc)^2 reduction, 2 float4-pairs per thread, 360 blocks
        int rbid = bid - NIOU;
        float s = 0.0f;
        int base_idx = rbid * (256*UNR) + tid;
        #pragma unroll
        for (int k = 0; k < UNR; k++) {
            int fidx = base_idx + k * 256;            // float4 index
            int plane = fidx / (HWSZ/4);
            int off   = fidx % (HWSZ/4);
            int b = plane / NBA, a = plane % NBA;
            size_t base = (size_t)(b*CC + a*LCH) * HWSZ + (size_t)off * 4;
            float4 t = *reinterpret_cast<const float4*>(T + base);
            float4 p = *reinterpret_cast<const float4*>(P + base);
            float dx = t.x - p.x, dy = t.y - p.y, dz = t.z - p.z, dw = t.w - p.w;
            s += dx*dx + dy*dy + dz*dz + dw*dw;
        }
        #pragma unroll
        for (int o = 16; o; o >>= 1) s += __shfl_down_sync(0xffffffffu, s, o);
        __shared__ float ws[8];
        if (lane == 0) ws[wd] = s;
        __syncthreads();
        if (tid == 0) {
            float bs = 0.0f;
            #pragma unroll
            for (int k = 0; k < 8; k++) bs += ws[k];
            g_part[rbid] = bs;
        }
    }

    // ---------------- Ticket: last block finalizes ----------------
    __shared__ int sIsLast;
    __syncthreads();
    __threadfence();
    if (tid == 0) {
        int t = atomicAdd(&g_ticket, 1);
        sIsLast = (t == NBLK - 1);
    }
    __syncthreads();
    if (!sIsLast) return;
    __threadfence();   // acquire: order staged-data reads after the ticket

    // ---------------- Phase 2: finalize (one block, 256 threads) ----------------
    __shared__ int    sB[NOBJ], sG[NOBJ], sH[NOBJ], sW[NOBJ];
    __shared__ int    sCand[NOBJ], sSel[NOBJ];
    __shared__ int    sMask[BB*NBA*NBA];
    __shared__ int    sDepKey[NOBJ], sDepJ[NOBJ];
    __shared__ int    sXYKey[NOBJ], sXYJ[NOBJ];
    __shared__ int    sRelList[NOBJ];
    __shared__ int    cntDep, cntXY;
    __shared__ int    warpCnt[8], warpBase[8];
    __shared__ int    tblKey[HSZ], tblMin[HSZ];
    __shared__ float  sRed[4][8];
    __shared__ double sDAll[8];

    if (tid == 0) { cntDep = 0; cntXY = 0; }
    int b = G[tid*4+0], g = G[tid*4+1], h = G[tid*4+2], w = G[tid*4+3];
    sB[tid] = b; sG[tid] = g; sH[tid] = h; sW[tid] = w;
    for (int k = tid; k < BB*NBA*NBA; k += 256) sMask[k] = 0;
    #pragma unroll
    for (int k = 0; k < HSZ/256; k++) {
        tblKey[tid + k*256] = -1;
        tblMin[tid + k*256] = 0x7fffffff;
    }

    // Dense-reduction partial sum (360 slots)
    double dsum = 0.0;
    for (int k = tid; k < NRED; k += 256) dsum += (double)g_part[k];
    #pragma unroll
    for (int o = 16; o; o >>= 1) dsum += __shfl_down_sync(0xffffffffu, dsum, o);
    if (lane == 0) sDAll[wd] = dsum;

    // Candidate bitmask + independent result
    int cand = 0;
    #pragma unroll
    for (int a = 1; a < NBA; a++)
        if (g_iou[tid*NBA + a] > 0.0f) cand |= (1 << a);
    sCand[tid] = cand;
    sSel[tid] = cand ? (__ffs(cand) - 1) : 0;   // default; serial pass overwrites relevant

    // Dependent grids (read-row writable): append read key (b,h,w)
    int dep = (w < NBA);
    if (dep) {
        int p = atomicAdd(&cntDep, 1);
        sDepKey[p] = (b << 16) | (h << 8) | w;
        sDepJ[p]   = tid;
    }
    // sel_xy sources: grids with w == h
    if (w == h) {
        int p = atomicAdd(&cntXY, 1);
        sXYKey[p] = (b << 16) | (g << 8) | h;
        sXYJ[p]   = tid;
    }
    __syncthreads();

    // Relevance: dep, or write-row (b,g,h) read by a LATER dependent grid
    int wkey = (b << 16) | (g << 8) | h;
    int rel = dep;
    int nd = cntDep;
    for (int t = 0; t < nd; t++)
        if (sDepKey[t] == wkey && sDepJ[t] > tid) rel = 1;

    // Ordered compaction of relevant indices (warp ballot)
    unsigned bal = __ballot_sync(0xffffffffu, rel);
    if (lane == 0) warpCnt[wd] = __popc(bal);
    __syncthreads();
    if (tid == 0) {
        int acc = 0;
        #pragma unroll
        for (int k = 0; k < 8; k++) { warpBase[k] = acc; acc += warpCnt[k]; }
        warpCnt[0] = acc;
    }
    __syncthreads();
    int nRel = warpCnt[0];
    if (rel) sRelList[warpBase[wd] + __popc(bal & ((1u << lane) - 1u))] = tid;
    __syncthreads();

    // Tiny serial pass (thread 0) over relevant grids only
    if (tid == 0) {
        for (int t = 0; t < nRel; t++) {
            int i  = sRelList[t];
            int bi = sB[i], gi = sG[i], hi = sH[i], wi = sW[i];
            int res;
            if (wi < NBA) {
                int m = sCand[i] & ~sMask[(bi*NBA + hi)*NBA + wi];
                res = m ? (__ffs(m) - 1) : 0;
            } else {
                res = sSel[i];
            }
            if (res) sMask[(bi*NBA + gi)*NBA + hi] |= (1 << res);
            sSel[i] = res;
        }
    }
    __syncthreads();

    // sel_xy: unique grid with (b,g,h, w==h) matching (b,g,h)
    int sxy = 0;
    int nxy = cntXY;
    for (int t = 0; t < nxy; t++)
        if (sXYKey[t] == wkey) sxy = sSel[sXYJ[t]];

    int sel = sSel[tid];

    // Dedup via linear-probing hash: first occurrence (min tid) per key wins.
    int dkey = ((((b*HH) + h)*WW + w) << 4) | sel;
    int slot = (int)(((unsigned)dkey * 0x9E3779B1u) >> 22);
    while (true) {
        int prev = atomicCAS(&tblKey[slot], -1, dkey);
        if (prev == -1 || prev == dkey) { atomicMin(&tblMin[slot], tid); break; }
        slot = (slot + 1) & (HSZ - 1);
    }
    __syncthreads();
    int isFirst;
    {
        int s2 = (int)(((unsigned)dkey * 0x9E3779B1u) >> 22);
        while (tblKey[s2] != dkey) s2 = (s2 + 1) & (HSZ - 1);
        isFirst = (tblMin[s2] == tid);
    }

    // Loss terms: 5 staged loads
    int ib = tid*NBA;
    float loc  = g_A1[ib + sxy] + g_A2[ib + sel];
    float cobj = g_A3[ib + sel];
    float cls  = g_A4[ib + sel];
    float corr = isFirst ? g_A5[ib + sel] : 0.0f;

    float v0 = loc, v1 = cobj, v2 = cls, v3 = corr;
    #pragma unroll
    for (int o = 16; o; o >>= 1) {
        v0 += __shfl_down_sync(0xffffffffu, v0, o);
        v1 += __shfl_down_sync(0xffffffffu, v1, o);
        v2 += __shfl_down_sync(0xffffffffu, v2, o);
        v3 += __shfl_down_sync(0xffffffffu, v3, o);
    }
    if (lane == 0) { sRed[0][wd] = v0; sRed[1][wd] = v1; sRed[2][wd] = v2; sRed[3][wd] = v3; }
    __syncthreads();
    if (tid == 0) {
        float L = 0, Cq = 0, Cl = 0, Co = 0;
        double all = 0.0;
        #pragma unroll
        for (int k = 0; k < 8; k++) {
            L += sRed[0][k]; Cq += sRed[1][k]; Cl += sRed[2][k]; Co += sRed[3][k];
            all += sDAll[k];
        }
        double nothing = (all - (double)Co) / (double)TOTAL;
        out[0] = 7.0f * (L / NOBJ) + 5.0f * (Cq / NOBJ)
               + 5.0f * (float)nothing + (Cl / NOBJ);
        g_ticket = 0;   // reset for next graph replay (deterministic)
    }
}

extern "C" void kernel_launch(void* const* d_in, const int* in_sizes, int n_in,
                              void* d_out, int out_size) {
    const float* P = (const float*)d_in[0];
    const float* T = (const float*)d_in[1];
    const int*   G = (const int*)d_in[2];
    float* out = (float*)d_out;

    kFused<<<NBLK, 256>>>(P, T, G, out);
}

// round 10
// speedup vs baseline: 6.3454x; 1.0019x over previous
#include <cuda_runtime.h>
#include <math.h>

#define NBA 10
#define NCLS 14
#define LCH 19
#define NOBJ 256
#define BB 8
#define HH 96
#define WW 96
#define CC (NBA*LCH)          // 190
#define HWSZ (HH*WW)          // 9216
#define TOTAL (BB*NBA*HH*WW)  // 737280
#define NF4 (TOTAL/4)         // 184320 float4 per tensor
#define PF4 (HWSZ/4)          // 2304 float4 per plane
#define DUNR 4                // float4-pairs per dense thread (front-batched)
#define NRED 180              // reduce blocks: 180*256*4 == NF4
#define NIOU 80               // gather blocks: 80 * 32 pairs == 2560
#define NBLK (NIOU + NRED)
#define HSZ 1024              // dedup hash slots (power of two)

// Staging (rewritten every replay -> deterministic, no zeroing needed)
__device__ float g_part[NRED];
__device__ float g_iou[NOBJ*NBA];
__device__ float g_A1 [NOBJ*NBA];   // (tx-px)^2 + (ty-py)^2
__device__ float g_A2 [NOBJ*NBA];   // (sqrt tw - sqrt pw)^2 + (sqrt th - sqrt ph)^2
__device__ float g_A3 [NOBJ*NBA];   // (tc - pc)^2
__device__ float g_A4 [NOBJ*NBA];   // mean_c (pcls - tcls)^2
__device__ float g_A5 [NOBJ*NBA];   // (tconf_a - pc)^2
__device__ int   g_ticket;          // starts 0; finalizer resets to 0 each replay

__global__ void __launch_bounds__(256, 2)
kFused(const float* __restrict__ P, const float* __restrict__ T,
       const int* __restrict__ G, float* __restrict__ out) {
    int bid = blockIdx.x, tid = threadIdx.x;
    int lane = tid & 31, wd = tid >> 5;

    // ---------------- Phase 1: staging work ----------------
    if (bid < NIOU) {
        // gather/IoU/loss-term staging: 8 threads per (grid,anchor) pair,
        // 32 pairs per block.
        __shared__ float sTB[32][4], sPB[32][4], sBoxP[32][4], sCls[32][8];
        int pl   = tid >> 3;                  // pair-local 0..31
        int slot = tid & 7;
        int pp   = bid * 32 + pl;             // 0 .. 2559
        int i = pp / NBA, a = pp % NBA;
        int4 gi = ((const int4*)G)[i];
        int b = gi.x, g = gi.y, h = gi.z, w = gi.w;
        int base = h * WW + w;
        const float* Tg   = T + (size_t)(b*CC + g*LCH)*HWSZ + base;
        const float* Pa   = P + (size_t)(b*CC + a*LCH)*HWSZ + base;
        const float* Tcls = T + (size_t)(b*CC + b*LCH + 5)*HWSZ + base; // bug-preserved

        // class partial: slot handles c=slot and (if slot<6) c=slot+8
        float clsPart;
        {
            float d = Pa[(size_t)(5 + slot)*HWSZ] - Tcls[(size_t)slot*HWSZ];
            clsPart = d * d;
            if (slot < 6) {
                float d2 = Pa[(size_t)(13 + slot)*HWSZ] - Tcls[(size_t)(8 + slot)*HWSZ];
                clsPart += d2 * d2;
            }
        }
        sCls[pl][slot] = clsPart;

        if (slot < 4) {
            float tcomp = Tg[(size_t)(1 + slot)*HWSZ];
            float pcomp = Pa[(size_t)(1 + slot)*HWSZ];
            sTB[pl][slot] = tcomp; sPB[pl][slot] = pcomp;
            float bp;
            if (slot < 2) { float d = tcomp - pcomp; bp = d * d; }
            else {
                float st = sqrtf(fmaxf(tcomp, 0.0f)), sp = sqrtf(fmaxf(pcomp, 0.0f));
                float d = st - sp; bp = d * d;
            }
            sBoxP[pl][slot] = bp;
        } else if (slot == 4) {
            float pc  = Pa[0];
            float tc  = Tg[0];
            float tcs = T[(size_t)(b*CC + a*LCH)*HWSZ + base];
            g_A3[pp] = (tc - pc)*(tc - pc);
            g_A5[pp] = (tcs - pc)*(tcs - pc);
        }
        __syncthreads();
        if (slot == 0) {
            float tx = sTB[pl][0], ty = sTB[pl][1], tw = sTB[pl][2], th = sTB[pl][3];
            float px = sPB[pl][0], py = sPB[pl][1], pw = sPB[pl][2], ph = sPB[pl][3];
            float tx1 = tx - tw*0.5f, ty1 = ty - th*0.5f, tx2 = tx + tw*0.5f, ty2 = ty + th*0.5f;
            float px1 = px - pw*0.5f, py1 = py - ph*0.5f, px2 = px + pw*0.5f, py2 = py + ph*0.5f;
            float x1 = fmaxf(tx1, px1), y1 = fmaxf(ty1, py1);
            float x2 = fminf(tx2, px2), y2 = fminf(ty2, py2);
            float inter = fmaxf(x2 - x1, 0.0f) * fmaxf(y2 - y1, 0.0f);
            float a1 = fabsf((tx2 - tx1) * (ty2 - ty1));
            float a2 = fabsf((px2 - px1) * (py2 - py1));
            g_iou[pp] = inter / (a1 + a2 - inter + 1e-6f);
            g_A1[pp] = sBoxP[pl][0] + sBoxP[pl][1];
            g_A2[pp] = sBoxP[pl][2] + sBoxP[pl][3];
            float cs = 0.0f;
            #pragma unroll
            for (int k = 0; k < 8; k++) cs += sCls[pl][k];
            g_A4[pp] = cs * (1.0f / NCLS);
        }
    } else {
        // dense (tc-pc)^2 reduction, front-batched: 4 float4 from T and 4 from P
        // held in registers simultaneously (MLP=8 per thread).
        int rbid = bid - NIOU;
        size_t addr[DUNR];
        #pragma unroll
        for (int k = 0; k < DUNR; k++) {
            int fidx = rbid * (256*DUNR) + k * 256 + tid;  // float4 index
            int plane = fidx / PF4;
            int off   = fidx % PF4;
            int b = plane / NBA, a = plane % NBA;
            addr[k] = (size_t)(b*CC + a*LCH) * HWSZ + (size_t)off * 4;
        }
        float4 tv[DUNR], pv[DUNR];
        #pragma unroll
        for (int k = 0; k < DUNR; k++)
            tv[k] = *reinterpret_cast<const float4*>(T + addr[k]);
        #pragma unroll
        for (int k = 0; k < DUNR; k++)
            pv[k] = *reinterpret_cast<const float4*>(P + addr[k]);
        float s = 0.0f;
        #pragma unroll
        for (int k = 0; k < DUNR; k++) {
            float dx = tv[k].x - pv[k].x, dy = tv[k].y - pv[k].y;
            float dz = tv[k].z - pv[k].z, dw = tv[k].w - pv[k].w;
            s += dx*dx + dy*dy + dz*dz + dw*dw;
        }
        #pragma unroll
        for (int o = 16; o; o >>= 1) s += __shfl_down_sync(0xffffffffu, s, o);
        __shared__ float ws[8];
        if (lane == 0) ws[wd] = s;
        __syncthreads();
        if (tid == 0) {
            float bs = 0.0f;
            #pragma unroll
            for (int k = 0; k < 8; k++) bs += ws[k];
            g_part[rbid] = bs;
        }
    }

    // ---------------- Ticket: last block finalizes ----------------
    __shared__ int sIsLast;
    __syncthreads();
    __threadfence();
    if (tid == 0) {
        int t = atomicAdd(&g_ticket, 1);
        sIsLast = (t == NBLK - 1);
    }
    __syncthreads();
    if (!sIsLast) return;
    __threadfence();   // acquire: order staged-data reads after the ticket

    // ---------------- Phase 2: finalize (one block, 256 threads) ----------------
    __shared__ int    sB[NOBJ], sG[NOBJ], sH[NOBJ], sW[NOBJ];
    __shared__ int    sCand[NOBJ], sSel[NOBJ];
    __shared__ int    sMask[BB*NBA*NBA];
    __shared__ int    sDepKey[NOBJ], sDepJ[NOBJ];
    __shared__ int    sXYKey[NOBJ], sXYJ[NOBJ];
    __shared__ int    sRelList[NOBJ];
    __shared__ int    cntDep, cntXY;
    __shared__ int    warpCnt[8], warpBase[8];
    __shared__ int    tblKey[HSZ], tblMin[HSZ];
    __shared__ float  sRed[4][8];
    __shared__ double sDAll[8];

    if (tid == 0) { cntDep = 0; cntXY = 0; }
    int b = G[tid*4+0], g = G[tid*4+1], h = G[tid*4+2], w = G[tid*4+3];
    sB[tid] = b; sG[tid] = g; sH[tid] = h; sW[tid] = w;
    for (int k = tid; k < BB*NBA*NBA; k += 256) sMask[k] = 0;
    #pragma unroll
    for (int k = 0; k < HSZ/256; k++) {
        tblKey[tid + k*256] = -1;
        tblMin[tid + k*256] = 0x7fffffff;
    }

    // Dense-reduction partial sum (180 slots)
    double dsum = (tid < NRED) ? (double)g_part[tid] : 0.0;
    #pragma unroll
    for (int o = 16; o; o >>= 1) dsum += __shfl_down_sync(0xffffffffu, dsum, o);
    if (lane == 0) sDAll[wd] = dsum;

    // Candidate bitmask + independent result
    int cand = 0;
    #pragma unroll
    for (int a = 1; a < NBA; a++)
        if (g_iou[tid*NBA + a] > 0.0f) cand |= (1 << a);
    sCand[tid] = cand;
    sSel[tid] = cand ? (__ffs(cand) - 1) : 0;   // default; serial pass overwrites relevant

    // Dependent grids (read-row writable): append read key (b,h,w)
    int dep = (w < NBA);
    if (dep) {
        int p = atomicAdd(&cntDep, 1);
        sDepKey[p] = (b << 16) | (h << 8) | w;
        sDepJ[p]   = tid;
    }
    // sel_xy sources: grids with w == h
    if (w == h) {
        int p = atomicAdd(&cntXY, 1);
        sXYKey[p] = (b << 16) | (g << 8) | h;
        sXYJ[p]   = tid;
    }
    __syncthreads();

    // Relevance: dep, or write-row (b,g,h) read by a LATER dependent grid
    int wkey = (b << 16) | (g << 8) | h;
    int rel = dep;
    int nd = cntDep;
    for (int t = 0; t < nd; t++)
        if (sDepKey[t] == wkey && sDepJ[t] > tid) rel = 1;

    // Ordered compaction of relevant indices (warp ballot)
    unsigned bal = __ballot_sync(0xffffffffu, rel);
    if (lane == 0) warpCnt[wd] = __popc(bal);
    __syncthreads();
    if (tid == 0) {
        int acc = 0;
        #pragma unroll
        for (int k = 0; k < 8; k++) { warpBase[k] = acc; acc += warpCnt[k]; }
        warpCnt[0] = acc;
    }
    __syncthreads();
    int nRel = warpCnt[0];
    if (rel) sRelList[warpBase[wd] + __popc(bal & ((1u << lane) - 1u))] = tid;
    __syncthreads();

    // Tiny serial pass (thread 0) over relevant grids only
    if (tid == 0) {
        for (int t = 0; t < nRel; t++) {
            int i  = sRelList[t];
            int bi = sB[i], gi = sG[i], hi = sH[i], wi = sW[i];
            int res;
            if (wi < NBA) {
                int m = sCand[i] & ~sMask[(bi*NBA + hi)*NBA + wi];
                res = m ? (__ffs(m) - 1) : 0;
            } else {
                res = sSel[i];
            }
            if (res) sMask[(bi*NBA + gi)*NBA + hi] |= (1 << res);
            sSel[i] = res;
        }
    }
    __syncthreads();

    // sel_xy: unique grid with (b,g,h, w==h) matching (b,g,h)
    int sxy = 0;
    int nxy = cntXY;
    for (int t = 0; t < nxy; t++)
        if (sXYKey[t] == wkey) sxy = sSel[sXYJ[t]];

    int sel = sSel[tid];

    // Dedup via linear-probing hash: first occurrence (min tid) per key wins.
    int dkey = ((((b*HH) + h)*WW + w) << 4) | sel;
    int slot = (int)(((unsigned)dkey * 0x9E3779B1u) >> 22);
    while (true) {
        int prev = atomicCAS(&tblKey[slot], -1, dkey);
        if (prev == -1 || prev == dkey) { atomicMin(&tblMin[slot], tid); break; }
        slot = (slot + 1) & (HSZ - 1);
    }
    __syncthreads();
    int isFirst;
    {
        int s2 = (int)(((unsigned)dkey * 0x9E3779B1u) >> 22);
        while (tblKey[s2] != dkey) s2 = (s2 + 1) & (HSZ - 1);
        isFirst = (tblMin[s2] == tid);
    }

    // Loss terms: 5 staged loads
    int ib = tid*NBA;
    float loc  = g_A1[ib + sxy] + g_A2[ib + sel];
    float cobj = g_A3[ib + sel];
    float cls  = g_A4[ib + sel];
    float corr = isFirst ? g_A5[ib + sel] : 0.0f;

    float v0 = loc, v1 = cobj, v2 = cls, v3 = corr;
    #pragma unroll
    for (int o = 16; o; o >>= 1) {
        v0 += __shfl_down_sync(0xffffffffu, v0, o);
        v1 += __shfl_down_sync(0xffffffffu, v1, o);
        v2 += __shfl_down_sync(0xffffffffu, v2, o);
        v3 += __shfl_down_sync(0xffffffffu, v3, o);
    }
    if (lane == 0) { sRed[0][wd] = v0; sRed[1][wd] = v1; sRed[2][wd] = v2; sRed[3][wd] = v3; }
    __syncthreads();
    if (tid == 0) {
        float L = 0, Cq = 0, Cl = 0, Co = 0;
        double all = 0.0;
        #pragma unroll
        for (int k = 0; k < 8; k++) {
            L += sRed[0][k]; Cq += sRed[1][k]; Cl += sRed[2][k]; Co += sRed[3][k];
            all += sDAll[k];
        }
        double nothing = (all - (double)Co) / (double)TOTAL;
        out[0] = 7.0f * (L / NOBJ) + 5.0f * (Cq / NOBJ)
               + 5.0f * (float)nothing + (Cl / NOBJ);
        g_ticket = 0;   // reset for next graph replay (deterministic)
    }
}

extern "C" void kernel_launch(void* const* d_in, const int* in_sizes, int n_in,
                              void* d_out, int out_size) {
    const float* P = (const float*)d_in[0];
    const float* T = (const float*)d_in[1];
    const int*   G = (const int*)d_in[2];
    float* out = (float*)d_out;

    kFused<<<NBLK, 256>>>(P, T, G, out);
}